// round 14
// baseline (speedup 1.0000x reference)
#include <cuda_runtime.h>
#include <math.h>

// x: [2048, 512, 7, 7] fp32.
#define NCH      512
#define HW       49
#define SLAB     (NCH * HW)      // 25088 floats / sample
#define SLAB4    (SLAB / 4)      // 6272 float4 / sample
#define NTHREADS 512
#define NWARPS   (NTHREADS / 32) // 16
#define EPS      1e-5f

// Phase-1 grouping: 4 channels = 196 floats = 49 float4, 16B-aligned start.
#define GROUPS_PER_WARP 8        // 8 groups * 4 ch = 32 channels per warp

// SLAB4 = 512*12 + 128 (phase-4 tiling)
#define FULL_BATCHES 3
#define REM_THREADS  128

__global__ __launch_bounds__(NTHREADS, 4)
void ModelNew_25056839205377_kernel(const float* __restrict__ x,
                                    float* __restrict__ out)
{
    __shared__ float ch[NCH + 1];   // y[c] -> gate[c]; +1 slack for c+1 read
    __shared__ float red[32];       // 16 sums, 16 sumsqs

    const int tid  = threadIdx.x;
    const int warp = tid >> 5;
    const int lane = tid & 31;
    const size_t base = (size_t)blockIdx.x * SLAB;
    const float* __restrict__ xp = x + base;
    const float4* __restrict__ x4 = (const float4*)xp;

    // ---- Phase 1: per-channel spatial sums via float4 group loads ----
    // Group m covers channels [4m, 4m+4) = float4 [49m, 49m+49).
    #pragma unroll 2
    for (int g = 0; g < GROUPS_PER_WARP; ++g) {
        const int m = warp * GROUPS_PER_WARP + g;
        const int C = m * 4;                       // first channel of group
        const float4* gp = x4 + 49 * m;

        float t0 = 0.f, t1 = 0.f, t2 = 0.f, t3 = 0.f;

        // pass 1: lanes 0..31 -> local elements e = 4*lane .. 4*lane+3
        {
            const float4 v = gp[lane];
            const int e = 4 * lane;
            const int c = e / HW;                  // 0..2 here
            const int r = e - c * HW;
            float sA = v.x, sB = 0.f;
            if (r < 48) sA += v.y; else sB += v.y;
            if (r < 47) sA += v.z; else sB += v.z;
            if (r < 46) sA += v.w; else sB += v.w;
            t0 += (c == 0) ? sA : 0.f;
            t1 += (c == 1) ? sA : ((c == 0) ? sB : 0.f);
            t2 += (c == 2) ? sA : ((c == 1) ? sB : 0.f);
            t3 += (c == 3) ? sA : ((c == 2) ? sB : 0.f);
        }
        // pass 2: lanes 0..16 -> local elements e = 4*(32+lane) .. +3  (c in {2,3})
        if (lane < 17) {
            const float4 v = gp[32 + lane];
            const int e = 4 * (32 + lane);
            const int c = e / HW;
            const int r = e - c * HW;
            float sA = v.x, sB = 0.f;
            if (r < 48) sA += v.y; else sB += v.y;
            if (r < 47) sA += v.z; else sB += v.z;
            if (r < 46) sA += v.w; else sB += v.w;
            t2 += (c == 2) ? sA : 0.f;
            t3 += (c == 3) ? sA : ((c == 2) ? sB : 0.f);
        }

        // 4 butterfly reductions over the warp
        #pragma unroll
        for (int o = 16; o > 0; o >>= 1) {
            t0 += __shfl_xor_sync(0xffffffffu, t0, o);
            t1 += __shfl_xor_sync(0xffffffffu, t1, o);
            t2 += __shfl_xor_sync(0xffffffffu, t2, o);
            t3 += __shfl_xor_sync(0xffffffffu, t3, o);
        }
        if (lane == 0) {
            ch[C + 0] = t0 * (1.0f / HW);
            ch[C + 1] = t1 * (1.0f / HW);
            ch[C + 2] = t2 * (1.0f / HW);
            ch[C + 3] = t3 * (1.0f / HW);
        }
    }
    __syncwarp();   // warp w reads back only its own ch[32w..32w+31]

    // ---- Phase 2: warp partials over own 32 channels ----
    const float y = ch[tid];
    float ys = y, y2 = y * y;
    #pragma unroll
    for (int o = 16; o > 0; o >>= 1) {
        ys += __shfl_xor_sync(0xffffffffu, ys, o);
        y2 += __shfl_xor_sync(0xffffffffu, y2, o);
    }
    if (lane == 0) { red[warp] = ys; red[16 + warp] = y2; }
    __syncthreads();                                   // barrier 1 of 2

    // ---- Phase 3: redundant final reduce in EVERY warp, then gates ----
    {
        float s1 = (lane < 16) ? red[lane]      : 0.0f;
        float s2 = (lane < 16) ? red[16 + lane] : 0.0f;
        #pragma unroll
        for (int o = 8; o > 0; o >>= 1) {
            s1 += __shfl_xor_sync(0xffffffffu, s1, o);
            s2 += __shfl_xor_sync(0xffffffffu, s2, o);
        }
        s1 = __shfl_sync(0xffffffffu, s1, 0);
        s2 = __shfl_sync(0xffffffffu, s2, 0);
        const float m   = s1 * (1.0f / NCH);
        const float mx2 = s2 * (1.0f / NCH);
        const float var = fmaxf(mx2 - m * m, 0.0f);
        const float inv = rsqrtf(var + EPS);
        const float z   = (y - m) * inv;
        ch[tid] = __expf(-z * z);   // gate (C_PARAM=2 -> -0.5*2*z^2 = -z^2)
    }
    if (tid == 0) ch[NCH] = 0.0f;   // slack slot for predicated c+1 reads
    __syncthreads();                                   // barrier 2 of 2

    // ---- Phase 4: re-read x (L2-hit, evict-first), gate, stream store ----
    float4* __restrict__ o4 = (float4*)(out + base);

    #pragma unroll
    for (int b = 0; b < FULL_BATCHES; ++b) {
        const int i0 = tid + (4 * b) * NTHREADS;
        // 4 independent 128b loads in flight before any store
        float4 v0 = __ldcs(x4 + i0 + 0 * NTHREADS);
        float4 v1 = __ldcs(x4 + i0 + 1 * NTHREADS);
        float4 v2 = __ldcs(x4 + i0 + 2 * NTHREADS);
        float4 v3 = __ldcs(x4 + i0 + 3 * NTHREADS);
        #pragma unroll
        for (int k = 0; k < 4; ++k) {
            float4& v = (k == 0) ? v0 : (k == 1) ? v1 : (k == 2) ? v2 : v3;
            const int e = (i0 + k * NTHREADS) * 4;
            const int c = e / HW;            // constant div -> mul+shift
            const int r = e - c * HW;        // 0..48
            const float g0 = ch[c];
            const float gn = ch[c + 1];
            v.x *= g0;
            v.y *= (r < 48) ? g0 : gn;
            v.z *= (r < 47) ? g0 : gn;
            v.w *= (r < 46) ? g0 : gn;
            __stcs(o4 + i0 + k * NTHREADS, v);
        }
    }
    // remainder: SLAB4 - 12*512 = 128 float4s
    if (tid < REM_THREADS) {
        const int i = tid + 12 * NTHREADS;
        float4 v = __ldcs(x4 + i);
        const int e = i * 4;
        const int c = e / HW;
        const int r = e - c * HW;
        const float g0 = ch[c];
        const float gn = ch[c + 1];
        v.x *= g0;
        v.y *= (r < 48) ? g0 : gn;
        v.z *= (r < 47) ? g0 : gn;
        v.w *= (r < 46) ? g0 : gn;
        __stcs(o4 + i, v);
    }
}

extern "C" void kernel_launch(void* const* d_in, const int* in_sizes, int n_in,
                              void* d_out, int out_size)
{
    const float* x = (const float*)d_in[0];
    float* out = (float*)d_out;
    const int nblocks = in_sizes[0] / SLAB;   // 2048 samples
    ModelNew_25056839205377_kernel<<<nblocks, NTHREADS>>>(x, out);
}